// round 13
// baseline (speedup 1.0000x reference)
#include <cuda_runtime.h>
#include <cstdint>
#include <cstddef>

#define S_LEN 2048
#define BATCH 512
#define VDIM  29
#define HDIM  128
#define KTOT  160            // 128 (h) + 29 (x) + 3 zero-pad, inline x
#define ROWS  4              // batch rows per CTA (128 CTAs, 512 threads)

// intermediate encoder state (static device scratch — no allocation)
__device__ float g_enc[BATCH * HDIM];

typedef unsigned long long ull;

__device__ __forceinline__ ull pack2(float lo, float hi) {
    ull r; asm("mov.b64 %0, {%1, %2};" : "=l"(r) : "f"(lo), "f"(hi)); return r;
}
__device__ __forceinline__ ull fma2(ull a, ull b, ull c) {
    ull d; asm("fma.rn.f32x2 %0, %1, %2, %3;" : "=l"(d) : "l"(a), "l"(b), "l"(c)); return d;
}
__device__ __forceinline__ void unpack2(ull v, float& lo, float& hi) {
    asm("mov.b64 {%0, %1}, %2;" : "=f"(lo), "=f"(hi) : "l"(v));
}
__device__ __forceinline__ float fast_tanh(float x) {
    float ax = fabsf(x);
    float t  = __expf(-2.0f * ax);                 // MUFU.EX2 path
    float r  = __fdividef(1.0f - t, 1.0f + t);     // MUFU.RCP path
    return copysignf(r, x);
}

// ---------------------------------------------------------------------------
// Encoder, j-ownership: 128 CTAs x 4 rows x 512 threads. Warp w: rowpair
// rp=w>>3 (rows 2rp,2rp+1), j-group jg=w&7. Lane = (j_sub = lane&15,
// k_half = lane>>4): owns column j = jg*16+j_sub over k in [k_half*80,+80)
// for both rows. Dot product completes in-lane + ONE shfl.xor(16); no
// cross-warp reduction, no partial array, ONE __syncthreads per step
// (state double-buffered). State rows stored plain; ulonglong2 reads feed
// fma2 b-operands directly (broadcast across the 16 lanes of a k-half).
// Weights (80 floats/lane, packed as 40 ull) loaded once via LDG.
// ---------------------------------------------------------------------------
__global__ void __launch_bounds__(512, 1) enc_kernel(
    const float* __restrict__ x, const float* __restrict__ We_ih,
    const float* __restrict__ We_hh, const float* __restrict__ be_ih,
    const float* __restrict__ be_hh)
{
    __shared__ float g[2][ROWS][KTOT];      // 5 KB, double-buffered state

    const int tid  = threadIdx.x;
    const int warp = tid >> 5, lane = tid & 31;
    const int rp   = warp >> 3;             // 0: rows 0,1   1: rows 2,3
    const int jg   = warp & 7;
    const int jsub = lane & 15;
    const int kh   = lane >> 4;             // k-half 0/1
    const int j    = jg * 16 + jsub;
    const int k0   = kh * 80;
    const int rowbase = blockIdx.x * ROWS;

    // per-lane weights Wc[j][k0..k0+79], Wc = [We_hh | We_ih | 0]
    ull wp[40];
    #pragma unroll
    for (int p = 0; p < 40; ++p) {
        const int ka = k0 + 2 * p, kb = ka + 1;
        float wa = (ka < HDIM) ? We_hh[j * HDIM + ka]
                 : ((ka < HDIM + VDIM) ? We_ih[j * VDIM + (ka - HDIM)] : 0.f);
        float wb = (kb < HDIM) ? We_hh[j * HDIM + kb]
                 : ((kb < HDIM + VDIM) ? We_ih[j * VDIM + (kb - HDIM)] : 0.f);
        wp[p] = pack2(wa, wb);
    }
    const float biasr = be_ih[j] + be_hh[j];

    // zero both buffers (h=0, pads=0), then x_0 into buffer 0
    for (int i = tid; i < 2 * ROWS * KTOT; i += 512) ((float*)g)[i] = 0.f;
    __syncthreads();
    if (tid < ROWS * VDIM) {
        int r = tid / VDIM, v = tid - r * VDIM;
        g[0][r][HDIM + v] = x[((size_t)(rowbase + r) * S_LEN) * VDIM + v];
    }
    __syncthreads();

    const int r0 = rp * 2, r1 = r0 + 1;
    const int wrow = r0 + kh;               // row this lane finalizes
    float* genc_out = g_enc + (rowbase + wrow) * HDIM + j;

    const bool xth = (tid < ROWS * VDIM);
    int xr_r = 0, xr_v = 0;
    if (xth) { xr_r = tid / VDIM; xr_v = tid - xr_r * VDIM; }
    const float* xsrc = x + ((size_t)(rowbase + xr_r) * S_LEN) * VDIM + xr_v;

    for (int t = 0; t < S_LEN; ++t) {
        float* gold = (float*)g[t & 1];
        float* gnew = (float*)g[(t & 1) ^ 1];

        // prefetch next step's x (LDG latency hidden under the GEMV)
        float xr = 0.f;
        if (xth && t + 1 < S_LEN) xr = xsrc[(size_t)(t + 1) * VDIM];

        const ulonglong2* p0 = (const ulonglong2*)(gold + r0 * KTOT + k0);
        const ulonglong2* p1 = (const ulonglong2*)(gold + r1 * KTOT + k0);
        ull A = 0, B = 0, C = 0, D = 0;
        #pragma unroll
        for (int i = 0; i < 20; ++i) {
            const ulonglong2 g0 = p0[i];    // LDS.128, broadcast (2 addrs/warp)
            const ulonglong2 g1 = p1[i];
            A = fma2(wp[2 * i],     g0.x, A);
            B = fma2(wp[2 * i + 1], g0.y, B);
            C = fma2(wp[2 * i],     g1.x, C);
            D = fma2(wp[2 * i + 1], g1.y, D);
        }
        float a0, a1, b0, b1, c0, c1, d0, d1;
        unpack2(A, a0, a1); unpack2(B, b0, b1);
        unpack2(C, c0, c1); unpack2(D, d0, d1);
        float s0 = (a0 + a1) + (b0 + b1);          // row r0, this k-half
        float s1 = (c0 + c1) + (d0 + d1);          // row r1, this k-half
        s0 += __shfl_xor_sync(0xffffffffu, s0, 16);
        s1 += __shfl_xor_sync(0xffffffffu, s1, 16);
        float h = fast_tanh(biasr + (kh ? s1 : s0));
        gnew[wrow * KTOT + j] = h;
        if (xth && t + 1 < S_LEN) gnew[xr_r * KTOT + HDIM + xr_v] = xr;
        if (t == S_LEN - 1) *genc_out = h;
        __syncthreads();                            // the ONLY barrier per step
    }
}

// ---------------------------------------------------------------------------
// Decoder: one warp per batch row, 128 CTAs x 4 warps. h in per-warp
// double-buffered SMEM (broadcast LDS.128), 8 FMA accumulators, MUFU tanh.
// NEW: lag-8 periodicity escape — fp32 contraction settles into an exact
// orbit; comparing the full warp state vs 8 steps ago (bitwise, __all_sync)
// catches periods 1/2/4/8, then the tail is filled with the exact 8-value
// pattern. Falls back to the full 2048 steps if it never fires.
// ---------------------------------------------------------------------------
__global__ void __launch_bounds__(128) dec_kernel(
    const float* __restrict__ Wd_ih, const float* __restrict__ Wd_hh,
    const float* __restrict__ bd_ih, const float* __restrict__ bd_hh,
    float* __restrict__ out)
{
    __shared__ float hbuf[2][4][32];
    const int warp = threadIdx.x >> 5, lane = threadIdx.x & 31;
    const int b = blockIdx.x * 4 + warp;
    const float* er = g_enc + b * HDIM;
    float e0 = er[lane], e1 = er[32 + lane], e2 = er[64 + lane], e3 = er[96 + lane];
    const bool act = lane < VDIM;
    const int vl = act ? lane : 0;

    float Wp[32];
    #pragma unroll
    for (int u = 0; u < 32; ++u) Wp[u] = (u < VDIM) ? Wd_hh[vl * VDIM + u] : 0.f;

    float din = bd_ih[vl] + bd_hh[vl];
    {
        const float* wi = Wd_ih + vl * HDIM;
        float s0 = 0, s1 = 0, s2 = 0, s3 = 0;
        #pragma unroll
        for (int k = 0; k < 32; ++k) {
            s0 += wi[k]      * __shfl_sync(0xffffffffu, e0, k);
            s1 += wi[32 + k] * __shfl_sync(0xffffffffu, e1, k);
            s2 += wi[64 + k] * __shfl_sync(0xffffffffu, e2, k);
            s3 += wi[96 + k] * __shfl_sync(0xffffffffu, e3, k);
        }
        din += (s0 + s1) + (s2 + s3);
    }

    hbuf[0][warp][lane] = 0.f;      // h_0 state
    __syncwarp();

    float* orow = out + (size_t)b * S_LEN * VDIM + lane;
    float hist[8];
    float hold = 0.f;               // state 8 steps back (step -1 state = 0)
    int s = 0;
    for (; s < S_LEN; ) {
        #pragma unroll
        for (int u = 0; u < 8; ++u) {
            const float* hv = hbuf[(s + u) & 1][warp];
            const float4 A = *(const float4*)(hv);
            const float4 B = *(const float4*)(hv + 4);
            const float4 C = *(const float4*)(hv + 8);
            const float4 D = *(const float4*)(hv + 12);
            const float4 E = *(const float4*)(hv + 16);
            const float4 F = *(const float4*)(hv + 20);
            const float4 G = *(const float4*)(hv + 24);
            const float4 H = *(const float4*)(hv + 28);
            float q0 = fmaf(Wp[0],  A.x, din), q1 = Wp[1]  * A.y;
            float q2 = Wp[2]  * A.z,           q3 = Wp[3]  * A.w;
            float q4 = Wp[4]  * B.x,           q5 = Wp[5]  * B.y;
            float q6 = Wp[6]  * B.z,           q7 = Wp[7]  * B.w;
            q0 = fmaf(Wp[8],  C.x, q0); q1 = fmaf(Wp[9],  C.y, q1);
            q2 = fmaf(Wp[10], C.z, q2); q3 = fmaf(Wp[11], C.w, q3);
            q4 = fmaf(Wp[12], D.x, q4); q5 = fmaf(Wp[13], D.y, q5);
            q6 = fmaf(Wp[14], D.z, q6); q7 = fmaf(Wp[15], D.w, q7);
            q0 = fmaf(Wp[16], E.x, q0); q1 = fmaf(Wp[17], E.y, q1);
            q2 = fmaf(Wp[18], E.z, q2); q3 = fmaf(Wp[19], E.w, q3);
            q4 = fmaf(Wp[20], F.x, q4); q5 = fmaf(Wp[21], F.y, q5);
            q6 = fmaf(Wp[22], F.z, q6); q7 = fmaf(Wp[23], F.w, q7);
            q0 = fmaf(Wp[24], G.x, q0); q1 = fmaf(Wp[25], G.y, q1);
            q2 = fmaf(Wp[26], G.z, q2); q3 = fmaf(Wp[27], G.w, q3);
            q4 = fmaf(Wp[28], H.x, q4); q5 = fmaf(Wp[29], H.y, q5);
            q6 = fmaf(Wp[30], H.z, q6); q7 = fmaf(Wp[31], H.w, q7);
            float hn = fast_tanh(((q0 + q1) + (q2 + q3)) + ((q4 + q5) + (q6 + q7)));
            hbuf[((s + u) & 1) ^ 1][warp][lane] = hn;
            if (act) orow[(size_t)(s + u) * VDIM] = hn;
            hist[u] = hn;
            __syncwarp();
        }
        s += 8;
        bool eq = __float_as_int(hist[7]) == __float_as_int(hold);
        hold = hist[7];
        if (__all_sync(0xffffffffu, eq)) break;   // whole state repeats: lag 8
    }
    if (act) {   // bit-exact periodic tail (period divides 8, phase aligned)
        for (; s < S_LEN; s += 8) {
            #pragma unroll
            for (int u = 0; u < 8; ++u)
                orow[(size_t)(s + u) * VDIM] = hist[u];
        }
    }
}

// ---------------------------------------------------------------------------
extern "C" void kernel_launch(void* const* d_in, const int* in_sizes, int n_in,
                              void* d_out, int out_size) {
    const float* x     = (const float*)d_in[0];
    const float* We_ih = (const float*)d_in[1];
    const float* We_hh = (const float*)d_in[2];
    const float* be_ih = (const float*)d_in[3];
    const float* be_hh = (const float*)d_in[4];
    const float* Wd_ih = (const float*)d_in[5];
    const float* Wd_hh = (const float*)d_in[6];
    const float* bd_ih = (const float*)d_in[7];
    const float* bd_hh = (const float*)d_in[8];
    float* out = (float*)d_out;

    enc_kernel<<<BATCH / ROWS, 512>>>(x, We_ih, We_hh, be_ih, be_hh);
    dec_kernel<<<BATCH / 4, 128>>>(Wd_ih, Wd_hh, bd_ih, bd_hh, out);
}